// round 11
// baseline (speedup 1.0000x reference)
#include <cuda_runtime.h>
#include <math.h>
#include <stdint.h>

// Problem constants
#define BB   256
#define KIN  8
#define CC   1152
#define JJ   10
#define DD   16
#define JD   160
#define XKC  9216          // KIN*CC

// 8-capsule sub-chunks (fragment granularity): 144 of them
#define NSUB 144
// GEMM1 blocks: 16-capsule chunks (K=128 as 2 sub-chunks) -> 72 chunks
#define NCH1 72
// GEMM2: 16-capsule chunks (M=128 rows), K=64 batch slice; 72 x 4
#define CB2  16
#define NCH2 72

#define SMEMB1 86656       // 5376 uint4 B frags (86016) + cs[160]
#define SMEMB2 86016       // B frags; reused for G staging (81920)

// ---------------------------------------------------------------------------
// Device globals (runtime allocation forbidden)
// ---------------------------------------------------------------------------
__device__ alignas(16) float g_spart[NCH1 * BB * JD];   // split-K partials (11.8MB)
__device__ alignas(16) uint4 g_xf1h[NSUB * 2 * 2048];   // GEMM1 A-frag hi (9.4MB)
__device__ alignas(16) uint4 g_xf1l[NSUB * 2 * 2048];   // GEMM1 A-frag lo
__device__ alignas(16) uint4 g_xf2h[NCH2 * 4 * 2048];   // GEMM2 A-frag hi
__device__ alignas(16) uint4 g_xf2l[NCH2 * 4 * 2048];   // GEMM2 A-frag lo
__device__ alignas(16) float2 g_wf[NSUB * 5120];        // W frag pairs (5.9MB)
__device__ alignas(16) uint4 g_vf[4 * 5120];            // v frags per b-slice (327KB)
__device__ alignas(16) float g_b[CC * JJ];              // routing logits

__device__ __forceinline__ uint32_t tf32r(float f) {
    uint32_t u; asm("cvt.rna.tf32.f32 %0, %1;" : "=r"(u) : "f"(f)); return u;
}
__device__ __forceinline__ void hilo(float v, uint32_t& h, uint32_t& l) {
    h = tf32r(v);
    l = tf32r(v - __uint_as_float(h));
}
__device__ __forceinline__ void mma8(float* d, const uint4& a,
                                     uint32_t b0, uint32_t b1) {
    asm volatile(
        "mma.sync.aligned.m16n8k8.row.col.f32.tf32.tf32.f32 "
        "{%0,%1,%2,%3}, {%4,%5,%6,%7}, {%8,%9}, {%0,%1,%2,%3};"
        : "+f"(d[0]), "+f"(d[1]), "+f"(d[2]), "+f"(d[3])
        : "r"(a.x), "r"(a.y), "r"(a.z), "r"(a.w), "r"(b0), "r"(b1));
}

// ---------------------------------------------------------------------------
// prepAll: all one-time fragment preparation in a single 720-block launch.
//   blocks [0,288): GEMM1 A-frags  (sub-chunk, b-half)
//   blocks [288,576): GEMM2 A-frags (chunk, b-slice)
//   blocks [576,720): W frag pairs  (sub-chunk)
// ---------------------------------------------------------------------------
__global__ void __launch_bounds__(256) prepAll(const float* __restrict__ x,
                                               const float* __restrict__ W) {
    int bid = blockIdx.x;
    if (bid < 288) {
        int sub = bid >> 1, half = bid & 1;
        int c0 = sub * 8, b0 = half * 128;
        size_t base = (size_t)bid * 2048;
#pragma unroll
        for (int i = threadIdx.x; i < 2048; i += 256) {
            int w = i >> 8, k8 = (i >> 5) & 7, lane = i & 31;
            int tig = lane & 3, g = lane >> 2;
            int m0 = w * 16 + g;
            const float* xb = x + (size_t)(b0 + m0) * XKC + (2 * tig) * CC + c0 + k8;
            uint4 h, l;
            hilo(xb[0], h.x, l.x);              // A[m0][kc]
            hilo(xb[8 * XKC], h.y, l.y);        // A[m0+8][kc]
            hilo(xb[CC], h.z, l.z);             // A[m0][kc+4] (kin+1)
            hilo(xb[8 * XKC + CC], h.w, l.w);   // A[m0+8][kc+4]
            g_xf1h[base + i] = h;
            g_xf1l[base + i] = l;
        }
    } else if (bid < 576) {
        int idx = bid - 288;
        int chunk = idx >> 2, slice = idx & 3;
        int c0 = chunk * CB2, b0 = slice * 64;
        size_t base = (size_t)idx * 2048;
#pragma unroll
        for (int i = threadIdx.x; i < 2048; i += 256) {
            int w = i >> 8, k8 = (i >> 5) & 7, lane = i & 31;
            int tig = lane & 3, g = lane >> 2;
            int kc = k8 * 8 + tig;
            const float* xb = x + (size_t)(b0 + kc) * XKC + w * CC + c0 + g;
            uint4 h, l;
            hilo(xb[0], h.x, l.x);              // XT[w*16+g][kc]
            hilo(xb[8], h.y, l.y);              // cl = g+8
            hilo(xb[4 * XKC], h.z, l.z);        // kc+4
            hilo(xb[4 * XKC + 8], h.w, l.w);
            g_xf2h[base + i] = h;
            g_xf2l[base + i] = l;
        }
    } else {
        int sub = bid - 576;
        int c0 = sub * 8;
        size_t base = (size_t)sub * 5120;
#pragma unroll
        for (int i = threadIdx.x; i < 5120; i += 256) {
            int k8 = i / 640, rem = i - k8 * 640, lane = rem / 20, nt = rem - lane * 20;
            int tig = lane & 3, g = lane >> 2;
            int n = nt * 8 + g;
            g_wf[base + i] = *(const float2*)(
                W + (size_t)(c0 + k8) * 1280 + n * 8 + 2 * tig);
        }
    }
}

// ---------------------------------------------------------------------------
// MMA accumulate pass over one K=64 sub-chunk (A streamed from gmem frags,
// B fragments in smem, stride-21 uint4, conflict-free LDS.128)
// ---------------------------------------------------------------------------
__device__ __forceinline__ void gemm_pass(const uint4* __restrict__ aH,
                                          const uint4* __restrict__ aL,
                                          const uint4* bb4, int tid,
                                          float d[20][4]) {
    int w = tid >> 5, lane = tid & 31;
    const uint4* ah = aH + w * 256 + lane;
    const uint4* al = aL + w * 256 + lane;
#pragma unroll
    for (int k8 = 0; k8 < 8; k8++) {
        uint4 h = ah[k8 * 32];
        uint4 l = al[k8 * 32];
        const uint4* bp = bb4 + (k8 * 32 + lane) * 21;
#pragma unroll
        for (int nt = 0; nt < 20; nt++) {
            uint4 bq = bp[nt];
            mma8(d[nt], h, bq.x, bq.y);   // hi*hi
            mma8(d[nt], h, bq.z, bq.w);   // hi*lo
            mma8(d[nt], l, bq.x, bq.y);   // lo*hi
        }
    }
}

// ---------------------------------------------------------------------------
// Kernel B (GEMM1): K=128 per block via 2 sub-chunk passes; grid (72,2).
// B = c_ij*W from g_wf (rebuilt per pass); partials -> g_spart[chunk].
// ---------------------------------------------------------------------------
__global__ void __launch_bounds__(256) kernB() {
    extern __shared__ float sm[];
    uint4* bb4 = (uint4*)sm;            // 5376 uint4 = 86016B
    float* cs = sm + 21504;             // 160 floats

    int tid = threadIdx.x;
    int cp = blockIdx.x, half = blockIdx.y;
    int c0 = cp * 16;

    // softmax for 16 capsules
    if (tid < 160) {
        int cl = tid / 10, j = tid - cl * 10;
        const float* br = g_b + (size_t)(c0 + cl) * JJ;
        float bv[JJ], mx = -1e30f;
#pragma unroll
        for (int q = 0; q < JJ; q++) { bv[q] = br[q]; mx = fmaxf(mx, bv[q]); }
        float sum = 0.f;
#pragma unroll
        for (int q = 0; q < JJ; q++) { bv[q] = expf(bv[q] - mx); sum += bv[q]; }
        cs[tid] = bv[j] / sum;
    }
    __syncthreads();

    float d[20][4];
#pragma unroll
    for (int nt = 0; nt < 20; nt++)
#pragma unroll
        for (int q = 0; q < 4; q++) d[nt][q] = 0.f;

#pragma unroll
    for (int p = 0; p < 2; p++) {
        int sub = cp * 2 + p;
        if (p) __syncthreads();   // previous pass finished reading B

        // B fragments for this sub-chunk: coalesced LDG.64, scale, hilo, STS
        const float2* wf = g_wf + (size_t)sub * 5120;
#pragma unroll
        for (int i = tid; i < 5120; i += 256) {
            int k8 = i / 640, rem = i - k8 * 640, lane = rem / 20,
                nt = rem - lane * 20;
            int g = lane >> 2;
            float sc = cs[(p * 8 + k8) * 10 + ((nt * 8 + g) >> 4)];
            float2 wv = wf[i];
            uint4 q;
            hilo(sc * wv.x, q.x, q.z);
            hilo(sc * wv.y, q.y, q.w);
            bb4[(k8 * 32 + lane) * 21 + nt] = q;
        }
        __syncthreads();

        const uint4* aH = g_xf1h + ((size_t)sub * 2 + half) * 2048;
        const uint4* aL = g_xf1l + ((size_t)sub * 2 + half) * 2048;
        gemm_pass(aH, aL, bb4, tid, d);
    }

    // direct fragment store (fully-coalesced 32B sectors per 4-lane group)
    int w = tid >> 5, lane = tid & 31, g = lane >> 2, tig = lane & 3;
    float* dst = g_spart + ((size_t)cp * BB + half * 128 + w * 16 + g) * JD
               + 2 * tig;
#pragma unroll
    for (int nt = 0; nt < 20; nt++) {
        *(float2*)(dst + nt * 8) = make_float2(d[nt][0], d[nt][1]);
        *(float2*)(dst + 8 * JD + nt * 8) = make_float2(d[nt][2], d[nt][3]);
    }
}

// ---------------------------------------------------------------------------
// Kernel C: reduce 72 split-K partials + squash; writes v-fragments g_vf
// (and d_out on the final iteration). grid 80, block 512.
// ---------------------------------------------------------------------------
__global__ void __launch_bounds__(512) kernC(float* __restrict__ out) {
    int idx = blockIdx.x * 512 + threadIdx.x;   // b*160 + n
    float s = 1e-5f;                            // ref adds 1e-5 BEFORE magnitudes
    const float* sp = g_spart + idx;
#pragma unroll 8
    for (int ch = 0; ch < NCH1; ch++)
        s += sp[(size_t)ch * (BB * JD)];

    float mag = s * s;
#pragma unroll
    for (int off = 8; off; off >>= 1)
        mag += __shfl_xor_sync(0xffffffffu, mag, off, 16);

    float v = s * (mag / ((1.f + mag) * sqrtf(mag)));

    // scatter v into fragment slots: slice = b>>6, kc = b&63
    int b = idx / JD, n = idx - b * JD;
    int slice = b >> 6, kc = b & 63;
    int k8 = kc >> 3, rr = kc & 7, tig = rr & 3, hf = rr >> 2;
    int lane = (n & 7) * 4 + tig, nt = n >> 3;
    uint32_t h, l;
    hilo(v, h, l);
    uint32_t* vq = (uint32_t*)&g_vf[(size_t)slice * 5120 + (k8 * 32 + lane) * 20 + nt];
    vq[hf] = h;          // .x (kc) or .y (kc+4)
    vq[2 + hf] = l;      // .z or .w

    if (out) out[idx] = v;                      // (B,J,D,1) same linearization
}

// ---------------------------------------------------------------------------
// Kernel D (GEMM2): G[128r x 160n] over 64-batch slice; agreement -> b_ij.
// grid (72,4), block 256.
// ---------------------------------------------------------------------------
__global__ void __launch_bounds__(256, 2) kernD(const float* __restrict__ W) {
    extern __shared__ float sm[];
    uint4* bb4 = (uint4*)sm;

    int tid = threadIdx.x;
    int chunk = blockIdx.x, slice = blockIdx.y;
    int c0 = chunk * CB2;

    // B fragments: pure coalesced copy from g_vf (pad stride 20 -> 21)
    const uint4* vf = g_vf + (size_t)slice * 5120;
#pragma unroll
    for (int i = tid; i < 5120; i += 256) {
        int k8 = i / 640, rem = i - k8 * 640, lane = rem / 20, nt = rem - lane * 20;
        bb4[(k8 * 32 + lane) * 21 + nt] = vf[i];
    }
    __syncthreads();

    float d[20][4];
#pragma unroll
    for (int nt = 0; nt < 20; nt++)
#pragma unroll
        for (int q = 0; q < 4; q++) d[nt][q] = 0.f;

    const uint4* aH = g_xf2h + ((size_t)chunk * 4 + slice) * 2048;
    const uint4* aL = g_xf2l + ((size_t)chunk * 4 + slice) * 2048;
    gemm_pass(aH, aL, bb4, tid, d);

    __syncthreads();   // all warps done reading B before overwrite

    // stage G tile 128x160 into smem (reuses B region)
    int w = tid >> 5, lane = tid & 31, g = lane >> 2, tig = lane & 3;
#pragma unroll
    for (int nt = 0; nt < 20; nt++) {
        *(float2*)(sm + (w * 16 + g) * JD + nt * 8 + 2 * tig) =
            make_float2(d[nt][0], d[nt][1]);
        *(float2*)(sm + (w * 16 + g + 8) * JD + nt * 8 + 2 * tig) =
            make_float2(d[nt][2], d[nt][3]);
    }
    __syncthreads();

    // agreement[c,j] = sum_{kin,d} W[c,j,d,kin] * G[(kin*16+cl)][(j*16+d)]
    if (tid < 160) {
        int cl = tid / 10, j = tid - cl * 10;
        const float* wr = W + (size_t)(c0 + cl) * 1280 + j * 128;
        float ag = 0.f;
#pragma unroll
        for (int kin = 0; kin < KIN; kin++)
#pragma unroll
            for (int d2 = 0; d2 < DD; d2++)
                ag = fmaf(wr[d2 * 8 + kin], sm[(kin * 16 + cl) * JD + j * 16 + d2], ag);
        atomicAdd(&g_b[(c0 + cl) * JJ + j], ag);
    }
}

// ---------------------------------------------------------------------------
// Host launcher (graph-capturable)
// ---------------------------------------------------------------------------
extern "C" void kernel_launch(void* const* d_in, const int* in_sizes, int n_in,
                              void* d_out, int out_size) {
    const float* x = (const float*)d_in[0];
    const float* W = (const float*)d_in[1];
    if (in_sizes[0] != BB * XKC) {   // defensive mapping by element count
        x = (const float*)d_in[1];
        W = (const float*)d_in[0];
    }

    cudaFuncSetAttribute(kernB, cudaFuncAttributeMaxDynamicSharedMemorySize, SMEMB1);
    cudaFuncSetAttribute(kernD, cudaFuncAttributeMaxDynamicSharedMemorySize, SMEMB2);

    void* pb = nullptr;
    cudaGetSymbolAddress(&pb, g_b);
    cudaMemsetAsync(pb, 0, CC * JJ * sizeof(float));   // b_ij = 0 each call

    prepAll<<<720, 256>>>(x, W);                       // all frags, one launch

    dim3 gB(NCH1, 2);    // (72, 2)
    dim3 gD(NCH2, 4);    // (72, 4)
    for (int it = 0; it < 4; it++) {
        kernB<<<gB, 256, SMEMB1>>>();                           // tensor GEMM1
        kernC<<<(BB * JD) / 512, 512>>>(it == 3 ? (float*)d_out : nullptr);
        if (it < 3)                                             // iter-4 agreement dead
            kernD<<<gD, 256, SMEMB2>>>(W);                      // tensor GEMM2
    }
}

// round 12
// speedup vs baseline: 1.0689x; 1.0689x over previous
#include <cuda_runtime.h>
#include <math.h>
#include <stdint.h>

// Problem constants
#define BB   256
#define KIN  8
#define CC   1152
#define JJ   10
#define DD   16
#define JD   160
#define XKC  9216          // KIN*CC

// 8-capsule sub-chunks (fragment granularity & GEMM1 blocks): 144
#define NSUB 144
// GEMM2: 16-capsule chunks (M=128 rows), K=64 batch slice; 72 x 4
#define CB2  16
#define NCH2 72

#define GST  161           // G staging stride (odd -> conflict-free agreement)

#define SMEMB1 86336       // 5376 uint4 B frags (86016) + cs[80]
#define SMEMB2 86016       // B frags (86016) >= G staging (128*161*4 = 82432)

// ---------------------------------------------------------------------------
// Device globals (runtime allocation forbidden)
// ---------------------------------------------------------------------------
__device__ alignas(16) float g_spart[NSUB * BB * JD];   // split-K partials (23.6MB)
__device__ alignas(16) uint4 g_xf1h[NSUB * 2 * 2048];   // GEMM1 A-frag hi (9.4MB)
__device__ alignas(16) uint4 g_xf1l[NSUB * 2 * 2048];   // GEMM1 A-frag lo
__device__ alignas(16) uint4 g_xf2h[NCH2 * 4 * 2048];   // GEMM2 A-frag hi
__device__ alignas(16) uint4 g_xf2l[NCH2 * 4 * 2048];   // GEMM2 A-frag lo
__device__ alignas(16) float2 g_wf[NSUB * 5120];        // W frag pairs (5.9MB)
__device__ alignas(16) uint4 g_vf[4 * 5120];            // v frags per b-slice (327KB)
__device__ alignas(16) float g_b[CC * JJ];              // routing logits

__device__ __forceinline__ uint32_t tf32r(float f) {
    uint32_t u; asm("cvt.rna.tf32.f32 %0, %1;" : "=r"(u) : "f"(f)); return u;
}
__device__ __forceinline__ void hilo(float v, uint32_t& h, uint32_t& l) {
    h = tf32r(v);
    l = tf32r(v - __uint_as_float(h));
}
__device__ __forceinline__ void mma8(float* d, const uint4& a,
                                     uint32_t b0, uint32_t b1) {
    asm volatile(
        "mma.sync.aligned.m16n8k8.row.col.f32.tf32.tf32.f32 "
        "{%0,%1,%2,%3}, {%4,%5,%6,%7}, {%8,%9}, {%0,%1,%2,%3};"
        : "+f"(d[0]), "+f"(d[1]), "+f"(d[2]), "+f"(d[3])
        : "r"(a.x), "r"(a.y), "r"(a.z), "r"(a.w), "r"(b0), "r"(b1));
}

// ---------------------------------------------------------------------------
// prepAll: all one-time fragment preparation in a single 720-block launch.
//   [0,288): GEMM1 A-frags (sub-chunk, b-half)
//   [288,576): GEMM2 A-frags (chunk, b-slice)
//   [576,720): W frag pairs (sub-chunk)
// ---------------------------------------------------------------------------
__global__ void __launch_bounds__(256) prepAll(const float* __restrict__ x,
                                               const float* __restrict__ W) {
    int bid = blockIdx.x;
    if (bid < 288) {
        int sub = bid >> 1, half = bid & 1;
        int c0 = sub * 8, b0 = half * 128;
        size_t base = (size_t)bid * 2048;
#pragma unroll
        for (int i = threadIdx.x; i < 2048; i += 256) {
            int w = i >> 8, k8 = (i >> 5) & 7, lane = i & 31;
            int tig = lane & 3, g = lane >> 2;
            int m0 = w * 16 + g;
            const float* xb = x + (size_t)(b0 + m0) * XKC + (2 * tig) * CC + c0 + k8;
            uint4 h, l;
            hilo(xb[0], h.x, l.x);              // A[m0][kc]
            hilo(xb[8 * XKC], h.y, l.y);        // A[m0+8][kc]
            hilo(xb[CC], h.z, l.z);             // A[m0][kc+4] (kin+1)
            hilo(xb[8 * XKC + CC], h.w, l.w);   // A[m0+8][kc+4]
            g_xf1h[base + i] = h;
            g_xf1l[base + i] = l;
        }
    } else if (bid < 576) {
        int idx = bid - 288;
        int chunk = idx >> 2, slice = idx & 3;
        int c0 = chunk * CB2, b0 = slice * 64;
        size_t base = (size_t)idx * 2048;
#pragma unroll
        for (int i = threadIdx.x; i < 2048; i += 256) {
            int w = i >> 8, k8 = (i >> 5) & 7, lane = i & 31;
            int tig = lane & 3, g = lane >> 2;
            int kc = k8 * 8 + tig;
            const float* xb = x + (size_t)(b0 + kc) * XKC + w * CC + c0 + g;
            uint4 h, l;
            hilo(xb[0], h.x, l.x);              // XT[w*16+g][kc]
            hilo(xb[8], h.y, l.y);              // cl = g+8
            hilo(xb[4 * XKC], h.z, l.z);        // kc+4
            hilo(xb[4 * XKC + 8], h.w, l.w);
            g_xf2h[base + i] = h;
            g_xf2l[base + i] = l;
        }
    } else {
        int sub = bid - 576;
        int c0 = sub * 8;
        size_t base = (size_t)sub * 5120;
#pragma unroll
        for (int i = threadIdx.x; i < 5120; i += 256) {
            int k8 = i / 640, rem = i - k8 * 640, lane = rem / 20, nt = rem - lane * 20;
            int tig = lane & 3, g = lane >> 2;
            int n = nt * 8 + g;
            g_wf[base + i] = *(const float2*)(
                W + (size_t)(c0 + k8) * 1280 + n * 8 + 2 * tig);
        }
    }
}

// ---------------------------------------------------------------------------
// MMA pass over one K=64 sub-chunk (A streamed from gmem frags via LDG.128,
// B fragments in smem, stride-21 uint4, conflict-free LDS.128)
// ---------------------------------------------------------------------------
__device__ __forceinline__ void gemm_pass(const uint4* __restrict__ aH,
                                          const uint4* __restrict__ aL,
                                          const uint4* bb4, int tid,
                                          float d[20][4]) {
    int w = tid >> 5, lane = tid & 31;
    const uint4* ah = aH + w * 256 + lane;
    const uint4* al = aL + w * 256 + lane;
#pragma unroll
    for (int k8 = 0; k8 < 8; k8++) {
        uint4 h = ah[k8 * 32];
        uint4 l = al[k8 * 32];
        const uint4* bp = bb4 + (k8 * 32 + lane) * 21;
#pragma unroll
        for (int nt = 0; nt < 20; nt++) {
            uint4 bq = bp[nt];
            mma8(d[nt], h, bq.x, bq.y);   // hi*hi
            mma8(d[nt], h, bq.z, bq.w);   // hi*lo
            mma8(d[nt], l, bq.x, bq.y);   // lo*hi
        }
    }
}

// ---------------------------------------------------------------------------
// Kernel B (GEMM1): K=64 per block; grid (144,2), block 256, 2 blocks/SM.
// B = c_ij*W from g_wf; fragment epilogue straight to g_spart[sub].
// ---------------------------------------------------------------------------
__global__ void __launch_bounds__(256, 2) kernB() {
    extern __shared__ float sm[];
    uint4* bb4 = (uint4*)sm;            // 5376 uint4 = 86016B
    float* cs = sm + 21504;             // 80 floats

    int tid = threadIdx.x;
    int sub = blockIdx.x, half = blockIdx.y;
    int c0 = sub * 8;

    // softmax for 8 capsules
    if (tid < 80) {
        int cl = tid / 10, j = tid - cl * 10;
        const float* br = g_b + (size_t)(c0 + cl) * JJ;
        float bv[JJ], mx = -1e30f;
#pragma unroll
        for (int q = 0; q < JJ; q++) { bv[q] = br[q]; mx = fmaxf(mx, bv[q]); }
        float sum = 0.f;
#pragma unroll
        for (int q = 0; q < JJ; q++) { bv[q] = expf(bv[q] - mx); sum += bv[q]; }
        cs[tid] = bv[j] / sum;
    }
    __syncthreads();

    // B fragments: coalesced LDG.64 from g_wf, scale, hilo, STS.128
    const float2* wf = g_wf + (size_t)sub * 5120;
#pragma unroll
    for (int i = tid; i < 5120; i += 256) {
        int k8 = i / 640, rem = i - k8 * 640, lane = rem / 20, nt = rem - lane * 20;
        int g = lane >> 2;
        float sc = cs[k8 * 10 + ((nt * 8 + g) >> 4)];   // cl = k8, j = n>>4
        float2 wv = wf[i];
        uint4 q;
        hilo(sc * wv.x, q.x, q.z);
        hilo(sc * wv.y, q.y, q.w);
        bb4[(k8 * 32 + lane) * 21 + nt] = q;
    }
    __syncthreads();

    float d[20][4];
#pragma unroll
    for (int nt = 0; nt < 20; nt++)
#pragma unroll
        for (int q = 0; q < 4; q++) d[nt][q] = 0.f;

    const uint4* aH = g_xf1h + ((size_t)sub * 2 + half) * 2048;
    const uint4* aL = g_xf1l + ((size_t)sub * 2 + half) * 2048;
    gemm_pass(aH, aL, bb4, tid, d);

    // direct fragment store
    int w = tid >> 5, lane = tid & 31, g = lane >> 2, tig = lane & 3;
    float* dst = g_spart + ((size_t)sub * BB + half * 128 + w * 16 + g) * JD
               + 2 * tig;
#pragma unroll
    for (int nt = 0; nt < 20; nt++) {
        *(float2*)(dst + nt * 8) = make_float2(d[nt][0], d[nt][1]);
        *(float2*)(dst + 8 * JD + nt * 8) = make_float2(d[nt][2], d[nt][3]);
    }
}

// ---------------------------------------------------------------------------
// Kernel C: reduce 144 split-K partials + squash; writes v-fragments g_vf
// (and d_out on the final iteration). grid 80, block 512.
// ---------------------------------------------------------------------------
__global__ void __launch_bounds__(512) kernC(float* __restrict__ out) {
    int idx = blockIdx.x * 512 + threadIdx.x;   // b*160 + n
    float s = 1e-5f;                            // ref adds 1e-5 BEFORE magnitudes
    const float* sp = g_spart + idx;
#pragma unroll 8
    for (int ch = 0; ch < NSUB; ch++)
        s += sp[(size_t)ch * (BB * JD)];

    float mag = s * s;
#pragma unroll
    for (int off = 8; off; off >>= 1)
        mag += __shfl_xor_sync(0xffffffffu, mag, off, 16);

    float v = s * (mag / ((1.f + mag) * sqrtf(mag)));

    // scatter v into fragment slots: slice = b>>6, kc = b&63
    int b = idx / JD, n = idx - b * JD;
    int slice = b >> 6, kc = b & 63;
    int k8 = kc >> 3, rr = kc & 7, tig = rr & 3, hf = rr >> 2;
    int lane = (n & 7) * 4 + tig, nt = n >> 3;
    uint32_t h, l;
    hilo(v, h, l);
    uint32_t* vq = (uint32_t*)&g_vf[(size_t)slice * 5120 + (k8 * 32 + lane) * 20 + nt];
    vq[hf] = h;          // .x (kc) or .y (kc+4)
    vq[2 + hf] = l;      // .z or .w

    if (out) out[idx] = v;                      // (B,J,D,1) same linearization
}

// ---------------------------------------------------------------------------
// Kernel D (GEMM2): G[128r x 160n] over 64-batch slice; agreement -> b_ij.
// grid (72,4), block 256. G staged at odd stride GST=161 -> conflict-free
// agreement reads (bank = kin*16+cl+j*16+d2 mod 32 covers all 32 banks).
// ---------------------------------------------------------------------------
__global__ void __launch_bounds__(256, 2) kernD(const float* __restrict__ W) {
    extern __shared__ float sm[];
    uint4* bb4 = (uint4*)sm;

    int tid = threadIdx.x;
    int chunk = blockIdx.x, slice = blockIdx.y;
    int c0 = chunk * CB2;

    // B fragments: pure coalesced copy from g_vf (pad stride 20 -> 21)
    const uint4* vf = g_vf + (size_t)slice * 5120;
#pragma unroll
    for (int i = tid; i < 5120; i += 256) {
        int k8 = i / 640, rem = i - k8 * 640, lane = rem / 20, nt = rem - lane * 20;
        bb4[(k8 * 32 + lane) * 21 + nt] = vf[i];
    }
    __syncthreads();

    float d[20][4];
#pragma unroll
    for (int nt = 0; nt < 20; nt++)
#pragma unroll
        for (int q = 0; q < 4; q++) d[nt][q] = 0.f;

    const uint4* aH = g_xf2h + ((size_t)chunk * 4 + slice) * 2048;
    const uint4* aL = g_xf2l + ((size_t)chunk * 4 + slice) * 2048;
    gemm_pass(aH, aL, bb4, tid, d);

    __syncthreads();   // all warps done reading B before overwrite

    // stage G tile 128 x 160 at stride 161 (scalar stores, ~2-way max)
    int w = tid >> 5, lane = tid & 31, g = lane >> 2, tig = lane & 3;
    {
        float* r0 = sm + (w * 16 + g) * GST + 2 * tig;
        float* r1 = sm + (w * 16 + g + 8) * GST + 2 * tig;
#pragma unroll
        for (int nt = 0; nt < 20; nt++) {
            r0[nt * 8] = d[nt][0]; r0[nt * 8 + 1] = d[nt][1];
            r1[nt * 8] = d[nt][2]; r1[nt * 8 + 1] = d[nt][3];
        }
    }
    __syncthreads();

    // agreement[c,j] = sum_{kin,d} W[c,j,d,kin] * G[(kin*16+cl)][(j*16+d)]
    // thread map: cl = tid&15, j = tid>>4  (conflict-free with GST=161)
    if (tid < 160) {
        int cl = tid & 15, j = tid >> 4;
        const float* wr = W + (size_t)(c0 + cl) * 1280 + j * 128;
        float ag = 0.f;
#pragma unroll
        for (int kin = 0; kin < KIN; kin++)
#pragma unroll
            for (int d2 = 0; d2 < DD; d2++)
                ag = fmaf(wr[d2 * 8 + kin], sm[(kin * 16 + cl) * GST + j * 16 + d2], ag);
        atomicAdd(&g_b[(c0 + cl) * JJ + j], ag);
    }
}

// ---------------------------------------------------------------------------
// Host launcher (graph-capturable)
// ---------------------------------------------------------------------------
extern "C" void kernel_launch(void* const* d_in, const int* in_sizes, int n_in,
                              void* d_out, int out_size) {
    const float* x = (const float*)d_in[0];
    const float* W = (const float*)d_in[1];
    if (in_sizes[0] != BB * XKC) {   // defensive mapping by element count
        x = (const float*)d_in[1];
        W = (const float*)d_in[0];
    }

    cudaFuncSetAttribute(kernB, cudaFuncAttributeMaxDynamicSharedMemorySize, SMEMB1);
    cudaFuncSetAttribute(kernD, cudaFuncAttributeMaxDynamicSharedMemorySize, SMEMB2);

    void* pb = nullptr;
    cudaGetSymbolAddress(&pb, g_b);
    cudaMemsetAsync(pb, 0, CC * JJ * sizeof(float));   // b_ij = 0 each call

    prepAll<<<720, 256>>>(x, W);                       // all frags, one launch

    dim3 gB(NSUB, 2);    // (144, 2)
    dim3 gD(NCH2, 4);    // (72, 4)
    for (int it = 0; it < 4; it++) {
        kernB<<<gB, 256, SMEMB1>>>();                           // tensor GEMM1
        kernC<<<(BB * JD) / 512, 512>>>(it == 3 ? (float*)d_out : nullptr);
        if (it < 3)                                             // iter-4 agreement dead
            kernD<<<gD, 256, SMEMB2>>>(W);                      // tensor GEMM2
    }
}

// round 13
// speedup vs baseline: 1.4018x; 1.3115x over previous
#include <cuda_runtime.h>
#include <math.h>
#include <stdint.h>

// Problem constants
#define BB   256
#define KIN  8
#define CC   1152
#define JJ   10
#define DD   16
#define JD   160
#define XKC  9216          // KIN*CC

// 8-capsule sub-chunks (fragment granularity & GEMM1 blocks): 144
#define NSUB 144
// GEMM2: 16-capsule chunks (M=128 rows), K=64 batch slice; 72 x 4
#define CB2  16
#define NCH2 72

#define SMEMB1 86336       // 5376 uint4 B frags (86016) + cs[80]
#define SMEMB2 86656       // 5376 uint4 B frags + sAg[160]

// ---------------------------------------------------------------------------
// Device globals (runtime allocation forbidden)
// ---------------------------------------------------------------------------
__device__ alignas(16) float g_spart[NSUB * BB * JD];   // split-K partials (23.6MB)
__device__ alignas(16) uint4 g_xf1h[NSUB * 2 * 2048];   // GEMM1 A-frag hi (9.4MB)
__device__ alignas(16) uint4 g_xf1l[NSUB * 2 * 2048];   // GEMM1 A-frag lo
__device__ alignas(16) uint4 g_xf2h[NCH2 * 4 * 2048];   // GEMM2 A-frag hi
__device__ alignas(16) uint4 g_xf2l[NCH2 * 4 * 2048];   // GEMM2 A-frag lo
__device__ alignas(16) float2 g_wf[NSUB * 5120];        // W frag pairs (5.9MB)
__device__ alignas(16) uint4 g_wa[NCH2 * 5120];         // agreement W quads (5.9MB)
__device__ alignas(16) uint4 g_vf[4 * 5120];            // v frags per b-slice (327KB)
__device__ alignas(16) float g_b[CC * JJ];              // routing logits

__device__ __forceinline__ uint32_t tf32r(float f) {
    uint32_t u; asm("cvt.rna.tf32.f32 %0, %1;" : "=r"(u) : "f"(f)); return u;
}
__device__ __forceinline__ void hilo(float v, uint32_t& h, uint32_t& l) {
    h = tf32r(v);
    l = tf32r(v - __uint_as_float(h));
}
__device__ __forceinline__ void mma8(float* d, const uint4& a,
                                     uint32_t b0, uint32_t b1) {
    asm volatile(
        "mma.sync.aligned.m16n8k8.row.col.f32.tf32.tf32.f32 "
        "{%0,%1,%2,%3}, {%4,%5,%6,%7}, {%8,%9}, {%0,%1,%2,%3};"
        : "+f"(d[0]), "+f"(d[1]), "+f"(d[2]), "+f"(d[3])
        : "r"(a.x), "r"(a.y), "r"(a.z), "r"(a.w), "r"(b0), "r"(b1));
}

// ---------------------------------------------------------------------------
// prepAll: all one-time fragment preparation in a single 792-block launch.
//   [0,288): GEMM1 A-frags (sub-chunk, b-half)
//   [288,576): GEMM2 A-frags (chunk, b-slice)
//   [576,720): W frag pairs (sub-chunk)
//   [720,792): agreement W quads (chunk)
// ---------------------------------------------------------------------------
__global__ void __launch_bounds__(256) prepAll(const float* __restrict__ x,
                                               const float* __restrict__ W) {
    int bid = blockIdx.x;
    if (bid < 288) {
        int sub = bid >> 1, half = bid & 1;
        int c0 = sub * 8, b0 = half * 128;
        size_t base = (size_t)bid * 2048;
#pragma unroll
        for (int i = threadIdx.x; i < 2048; i += 256) {
            int w = i >> 8, k8 = (i >> 5) & 7, lane = i & 31;
            int tig = lane & 3, g = lane >> 2;
            int m0 = w * 16 + g;
            const float* xb = x + (size_t)(b0 + m0) * XKC + (2 * tig) * CC + c0 + k8;
            uint4 h, l;
            hilo(xb[0], h.x, l.x);              // A[m0][kc]
            hilo(xb[8 * XKC], h.y, l.y);        // A[m0+8][kc]
            hilo(xb[CC], h.z, l.z);             // A[m0][kc+4] (kin+1)
            hilo(xb[8 * XKC + CC], h.w, l.w);   // A[m0+8][kc+4]
            g_xf1h[base + i] = h;
            g_xf1l[base + i] = l;
        }
    } else if (bid < 576) {
        int idx = bid - 288;
        int chunk = idx >> 2, slice = idx & 3;
        int c0 = chunk * CB2, b0 = slice * 64;
        size_t base = (size_t)idx * 2048;
#pragma unroll
        for (int i = threadIdx.x; i < 2048; i += 256) {
            int w = i >> 8, k8 = (i >> 5) & 7, lane = i & 31;
            int tig = lane & 3, g = lane >> 2;
            int kc = k8 * 8 + tig;
            const float* xb = x + (size_t)(b0 + kc) * XKC + w * CC + c0 + g;
            uint4 h, l;
            hilo(xb[0], h.x, l.x);              // XT[w*16+g][kc]
            hilo(xb[8], h.y, l.y);              // cl = g+8
            hilo(xb[4 * XKC], h.z, l.z);        // kc+4
            hilo(xb[4 * XKC + 8], h.w, l.w);
            g_xf2h[base + i] = h;
            g_xf2l[base + i] = l;
        }
    } else if (bid < 720) {
        int sub = bid - 576;
        int c0 = sub * 8;
        size_t base = (size_t)sub * 5120;
#pragma unroll
        for (int i = threadIdx.x; i < 5120; i += 256) {
            int k8 = i / 640, rem = i - k8 * 640, lane = rem / 20, nt = rem - lane * 20;
            int tig = lane & 3, g = lane >> 2;
            int n = nt * 8 + g;
            g_wf[base + i] = *(const float2*)(
                W + (size_t)(c0 + k8) * 1280 + n * 8 + 2 * tig);
        }
    } else {
        // agreement W quads: g_wa[chunk][(w*20+nt)*32+lane] =
        //  {W[c0+g, n, w], W[c0+g, n+1, w], W[c0+g+8, n, w], W[c0+g+8, n+1, w]}
        //  with n = nt*8 + 2*tig
        int chunk = bid - 720;
        int c0 = chunk * CB2;
        size_t base = (size_t)chunk * 5120;
#pragma unroll
        for (int i = threadIdx.x; i < 5120; i += 256) {
            int w = i / 640, rem = i - w * 640, nt = rem >> 5, lane = rem & 31;
            int tig = lane & 3, g = lane >> 2;
            int n = nt * 8 + 2 * tig;
            const float* w0 = W + (size_t)(c0 + g) * 1280 + n * 8 + w;
            const float* w1 = W + (size_t)(c0 + g + 8) * 1280 + n * 8 + w;
            uint4 q;
            q.x = __float_as_uint(w0[0]);
            q.y = __float_as_uint(w0[8]);
            q.z = __float_as_uint(w1[0]);
            q.w = __float_as_uint(w1[8]);
            g_wa[base + i] = q;
        }
    }
}

// ---------------------------------------------------------------------------
// MMA pass over one K=64 sub-chunk (A streamed from gmem frags via LDG.128,
// B fragments in smem, stride-21 uint4, conflict-free LDS.128)
// ---------------------------------------------------------------------------
__device__ __forceinline__ void gemm_pass(const uint4* __restrict__ aH,
                                          const uint4* __restrict__ aL,
                                          const uint4* bb4, int tid,
                                          float d[20][4]) {
    int w = tid >> 5, lane = tid & 31;
    const uint4* ah = aH + w * 256 + lane;
    const uint4* al = aL + w * 256 + lane;
#pragma unroll
    for (int k8 = 0; k8 < 8; k8++) {
        uint4 h = ah[k8 * 32];
        uint4 l = al[k8 * 32];
        const uint4* bp = bb4 + (k8 * 32 + lane) * 21;
#pragma unroll
        for (int nt = 0; nt < 20; nt++) {
            uint4 bq = bp[nt];
            mma8(d[nt], h, bq.x, bq.y);   // hi*hi
            mma8(d[nt], h, bq.z, bq.w);   // hi*lo
            mma8(d[nt], l, bq.x, bq.y);   // lo*hi
        }
    }
}

// ---------------------------------------------------------------------------
// Kernel B (GEMM1): K=64 per block; grid (144,2), block 256, 2 blocks/SM.
// ---------------------------------------------------------------------------
__global__ void __launch_bounds__(256, 2) kernB() {
    extern __shared__ float sm[];
    uint4* bb4 = (uint4*)sm;            // 5376 uint4 = 86016B
    float* cs = sm + 21504;             // 80 floats

    int tid = threadIdx.x;
    int sub = blockIdx.x, half = blockIdx.y;
    int c0 = sub * 8;

    // softmax for 8 capsules
    if (tid < 80) {
        int cl = tid / 10, j = tid - cl * 10;
        const float* br = g_b + (size_t)(c0 + cl) * JJ;
        float bv[JJ], mx = -1e30f;
#pragma unroll
        for (int q = 0; q < JJ; q++) { bv[q] = br[q]; mx = fmaxf(mx, bv[q]); }
        float sum = 0.f;
#pragma unroll
        for (int q = 0; q < JJ; q++) { bv[q] = expf(bv[q] - mx); sum += bv[q]; }
        cs[tid] = bv[j] / sum;
    }
    __syncthreads();

    // B fragments: coalesced LDG.64 from g_wf, scale, hilo, STS.128
    const float2* wf = g_wf + (size_t)sub * 5120;
#pragma unroll
    for (int i = tid; i < 5120; i += 256) {
        int k8 = i / 640, rem = i - k8 * 640, lane = rem / 20, nt = rem - lane * 20;
        int g = lane >> 2;
        float sc = cs[k8 * 10 + ((nt * 8 + g) >> 4)];   // cl = k8, j = n>>4
        float2 wv = wf[i];
        uint4 q;
        hilo(sc * wv.x, q.x, q.z);
        hilo(sc * wv.y, q.y, q.w);
        bb4[(k8 * 32 + lane) * 21 + nt] = q;
    }
    __syncthreads();

    float d[20][4];
#pragma unroll
    for (int nt = 0; nt < 20; nt++)
#pragma unroll
        for (int q = 0; q < 4; q++) d[nt][q] = 0.f;

    const uint4* aH = g_xf1h + ((size_t)sub * 2 + half) * 2048;
    const uint4* aL = g_xf1l + ((size_t)sub * 2 + half) * 2048;
    gemm_pass(aH, aL, bb4, tid, d);

    // direct fragment store
    int w = tid >> 5, lane = tid & 31, g = lane >> 2, tig = lane & 3;
    float* dst = g_spart + ((size_t)sub * BB + half * 128 + w * 16 + g) * JD
               + 2 * tig;
#pragma unroll
    for (int nt = 0; nt < 20; nt++) {
        *(float2*)(dst + nt * 8) = make_float2(d[nt][0], d[nt][1]);
        *(float2*)(dst + 8 * JD + nt * 8) = make_float2(d[nt][2], d[nt][3]);
    }
}

// ---------------------------------------------------------------------------
// Kernel C: reduce 144 split-K partials + squash; writes v-fragments g_vf
// (and d_out on the final iteration). grid 80, block 512.
// ---------------------------------------------------------------------------
__global__ void __launch_bounds__(512) kernC(float* __restrict__ out) {
    int idx = blockIdx.x * 512 + threadIdx.x;   // b*160 + n
    float s = 1e-5f;                            // ref adds 1e-5 BEFORE magnitudes
    const float* sp = g_spart + idx;
#pragma unroll 8
    for (int ch = 0; ch < NSUB; ch++)
        s += sp[(size_t)ch * (BB * JD)];

    float mag = s * s;
#pragma unroll
    for (int off = 8; off; off >>= 1)
        mag += __shfl_xor_sync(0xffffffffu, mag, off, 16);

    float v = s * (mag / ((1.f + mag) * sqrtf(mag)));

    // scatter v into fragment slots: slice = b>>6, kc = b&63
    int b = idx / JD, n = idx - b * JD;
    int slice = b >> 6, kc = b & 63;
    int k8 = kc >> 3, rr = kc & 7, tig = rr & 3, hf = rr >> 2;
    int lane = (n & 7) * 4 + tig, nt = n >> 3;
    uint32_t h, l;
    hilo(v, h, l);
    uint32_t* vq = (uint32_t*)&g_vf[(size_t)slice * 5120 + (k8 * 32 + lane) * 20 + nt];
    vq[hf] = h;          // .x (kc) or .y (kc+4)
    vq[2 + hf] = l;      // .z or .w

    if (out) out[idx] = v;                      // (B,J,D,1) same linearization
}

// ---------------------------------------------------------------------------
// Kernel D (GEMM2): G over 64-batch slice, agreement computed ENTIRELY in
// fragment space (no G staging, no scattered W reads). grid (72,4), block 256.
// ---------------------------------------------------------------------------
__global__ void __launch_bounds__(256, 2) kernD() {
    extern __shared__ float sm[];
    uint4* bb4 = (uint4*)sm;            // 5376 uint4
    float* sAg = sm + 21504;            // 160 floats: agreement[cl][j]

    int tid = threadIdx.x;
    int chunk = blockIdx.x, slice = blockIdx.y;
    int c0 = chunk * CB2;

    if (tid < 160) sAg[tid] = 0.f;

    // B fragments: pure coalesced copy from g_vf (pad stride 20 -> 21)
    const uint4* vf = g_vf + (size_t)slice * 5120;
#pragma unroll
    for (int i = tid; i < 5120; i += 256) {
        int k8 = i / 640, rem = i - k8 * 640, lane = rem / 20, nt = rem - lane * 20;
        bb4[(k8 * 32 + lane) * 21 + nt] = vf[i];
    }
    __syncthreads();

    float d[20][4];
#pragma unroll
    for (int nt = 0; nt < 20; nt++)
#pragma unroll
        for (int q = 0; q < 4; q++) d[nt][q] = 0.f;

    const uint4* aH = g_xf2h + ((size_t)chunk * 4 + slice) * 2048;
    const uint4* aL = g_xf2l + ((size_t)chunk * 4 + slice) * 2048;
    gemm_pass(aH, aL, bb4, tid, d);

    // fragment-space agreement: thread (w=kin, lane) holds
    //   d[nt] = {G[kin*16+g][n], G[..][n+1], G[kin*16+g+8][n], G[..][n+1]},
    //   n = nt*8+2tig, and j = n>>4 = nt>>1 exactly.
    int w = tid >> 5, lane = tid & 31, g = lane >> 2, tig = lane & 3;
    float ag0[10], ag1[10];
#pragma unroll
    for (int j = 0; j < 10; j++) { ag0[j] = 0.f; ag1[j] = 0.f; }

    const uint4* wap = g_wa + (size_t)chunk * 5120 + w * 640 + lane;
#pragma unroll
    for (int nt = 0; nt < 20; nt++) {
        uint4 q = wap[nt * 32];
        float wx = __uint_as_float(q.x), wy = __uint_as_float(q.y);
        float wz = __uint_as_float(q.z), ww = __uint_as_float(q.w);
        int j = nt >> 1;
        ag0[j] = fmaf(wx, d[nt][0], fmaf(wy, d[nt][1], ag0[j]));
        ag1[j] = fmaf(wz, d[nt][2], fmaf(ww, d[nt][3], ag1[j]));
    }
    // reduce across the 4 tig lanes (same g)
#pragma unroll
    for (int j = 0; j < 10; j++) {
        ag0[j] += __shfl_xor_sync(0xffffffffu, ag0[j], 1, 4);
        ag0[j] += __shfl_xor_sync(0xffffffffu, ag0[j], 2, 4);
        ag1[j] += __shfl_xor_sync(0xffffffffu, ag1[j], 1, 4);
        ag1[j] += __shfl_xor_sync(0xffffffffu, ag1[j], 2, 4);
    }
    if (tig == 0) {
#pragma unroll
        for (int j = 0; j < 10; j++) {
            atomicAdd(&sAg[g * 10 + j], ag0[j]);
            atomicAdd(&sAg[(g + 8) * 10 + j], ag1[j]);
        }
    }
    __syncthreads();

    if (tid < 160)
        atomicAdd(&g_b[c0 * JJ + tid], sAg[tid]);   // [cl][j] contiguous
}

// ---------------------------------------------------------------------------
// Host launcher (graph-capturable)
// ---------------------------------------------------------------------------
extern "C" void kernel_launch(void* const* d_in, const int* in_sizes, int n_in,
                              void* d_out, int out_size) {
    const float* x = (const float*)d_in[0];
    const float* W = (const float*)d_in[1];
    if (in_sizes[0] != BB * XKC) {   // defensive mapping by element count
        x = (const float*)d_in[1];
        W = (const float*)d_in[0];
    }

    cudaFuncSetAttribute(kernB, cudaFuncAttributeMaxDynamicSharedMemorySize, SMEMB1);
    cudaFuncSetAttribute(kernD, cudaFuncAttributeMaxDynamicSharedMemorySize, SMEMB2);

    void* pb = nullptr;
    cudaGetSymbolAddress(&pb, g_b);
    cudaMemsetAsync(pb, 0, CC * JJ * sizeof(float));   // b_ij = 0 each call

    prepAll<<<792, 256>>>(x, W);                       // all frags, one launch

    dim3 gB(NSUB, 2);    // (144, 2)
    dim3 gD(NCH2, 4);    // (72, 4)
    for (int it = 0; it < 4; it++) {
        kernB<<<gB, 256, SMEMB1>>>();                           // tensor GEMM1
        kernC<<<(BB * JD) / 512, 512>>>(it == 3 ? (float*)d_out : nullptr);
        if (it < 3)                                             // iter-4 agreement dead
            kernD<<<gD, 256, SMEMB2>>>();                       // tensor GEMM2
    }
}